// round 16
// baseline (speedup 1.0000x reference)
#include <cuda_runtime.h>
#include <cuda_fp16.h>

#define NNODES 100000
#define NEDGES 3200000
#define INCH 128
#define HID 64
#define SCAN_B 1024

// ---------------- scratch (static device globals; no allocs allowed) ----------------
__device__ __half d_g16[(size_t)NNODES * HID]; // fp16 messages (gather source)
__device__ float  d_h[(size_t)NNODES * HID];   // layer intermediate (fp32)
__device__ __half d_nr16[(size_t)NNODES * HID];// fp16 copy of node_representation
__device__ float  d_dinv[NNODES];
__device__ int    d_cnt[NNODES];               // in-degree (excl self loop)
__device__ int    d_off[NNODES + 1];           // CSR offsets
__device__ int    d_cur[NNODES];               // placement cursors
__device__ int    d_bsum[256];                 // per-block scan partials
__device__ int    d_srcs[NEDGES];              // CSR: source node per incoming edge
__device__ int    g_idx64;

// ---------------- side stream + events for fork/join (created once, host-side) ------
struct SideCtx {
    cudaStream_t side;
    cudaEvent_t evA, evB, evC, evD;
    SideCtx() {
        cudaStreamCreateWithFlags(&side, cudaStreamNonBlocking);
        cudaEventCreateWithFlags(&evA, cudaEventDisableTiming);
        cudaEventCreateWithFlags(&evB, cudaEventDisableTiming);
        cudaEventCreateWithFlags(&evC, cudaEventDisableTiming);
        cudaEventCreateWithFlags(&evD, cudaEventDisableTiming);
    }
};
static SideCtx g_ctx;

// ---------------- helpers ----------------
__device__ __forceinline__ unsigned long long pack2(float v) {
    unsigned long long r;
    asm("mov.b64 %0, {%1, %1};" : "=l"(r) : "f"(v));
    return r;
}
__device__ __forceinline__ void fma2(unsigned long long& acc, unsigned long long a,
                                     unsigned long long b) {
    asm("fma.rn.f32x2 %0, %1, %2, %0;" : "+l"(acc) : "l"(a), "l"(b));
}
__device__ __forceinline__ float2 unpack2(unsigned long long v) {
    float2 r;
    asm("mov.b64 {%0, %1}, %2;" : "=f"(r.x), "=f"(r.y) : "l"(v));
    return r;
}
__device__ __forceinline__ void decode_edge(const void* ei, int E, int i,
                                            int& r, int& c) {
    if (g_idx64) {
        const long long* p = (const long long*)ei;
        r = (int)p[i];
        c = (int)p[(size_t)E + i];
    } else {
        const int* p = (const int*)ei;
        r = p[i];
        c = p[(size_t)E + i];
    }
}
__device__ __forceinline__ int decode_col(const void* ei, int E, int i) {
    if (g_idx64) return (int)((const long long*)ei)[(size_t)E + i];
    return ((const int*)ei)[(size_t)E + i];
}

// ---------------- dtype detection: int64 edge_index has zero high words --------------
__global__ void detect_kernel(const unsigned* __restrict__ ei) {
    unsigned v = 0;
    int i = threadIdx.x;
#pragma unroll
    for (int s = 0; s < 4; ++s) v |= ei[(size_t)(i * 4 + s) * 2 + 1];
    unsigned any = __ballot_sync(0xffffffffu, v != 0);
    if (threadIdx.x == 0) g_idx64 = (any == 0) ? 1 : 0;
}

__global__ void init_cnt_kernel(int n) {
    int i = blockIdx.x * blockDim.x + threadIdx.x;
    if (i < n) d_cnt[i] = 0;
}

// ---------------- in-degree histogram (inline decode) -------------------------------
__global__ void hist_kernel(const void* __restrict__ ei, int E) {
    int i = blockIdx.x * blockDim.x + threadIdx.x;
    if (i >= E) return;
    atomicAdd(&d_cnt[decode_col(ei, E, i)], 1);
}

// ---------------- multi-block exclusive scan: 3 phases -------------------------------
__global__ __launch_bounds__(SCAN_B) void scan1_kernel(int n) {
    __shared__ int swarp[32];
    int t = threadIdx.x, lane = t & 31, wid = t >> 5;
    int i = blockIdx.x * SCAN_B + t;
    int v = (i < n) ? d_cnt[i] : 0;
    int incl = v;
#pragma unroll
    for (int o = 1; o < 32; o <<= 1) {
        int x = __shfl_up_sync(0xffffffffu, incl, o);
        if (lane >= o) incl += x;
    }
    if (lane == 31) swarp[wid] = incl;
    __syncthreads();
    if (wid == 0) {
        int wv = swarp[lane];
        int winc = wv;
#pragma unroll
        for (int o = 1; o < 32; o <<= 1) {
            int x = __shfl_up_sync(0xffffffffu, winc, o);
            if (lane >= o) winc += x;
        }
        swarp[lane] = winc - wv;
        if (lane == 31) d_bsum[blockIdx.x] = winc;
    }
    __syncthreads();
    if (i < n) d_off[i] = incl - v + swarp[wid];
}

__global__ void scan2_kernel(int nb) {
    __shared__ int swarp[32];
    int t = threadIdx.x, lane = t & 31, wid = t >> 5; // 256 threads
    int v = (t < nb) ? d_bsum[t] : 0;
    int incl = v;
#pragma unroll
    for (int o = 1; o < 32; o <<= 1) {
        int x = __shfl_up_sync(0xffffffffu, incl, o);
        if (lane >= o) incl += x;
    }
    if (lane == 31) swarp[wid] = incl;
    __syncthreads();
    if (wid == 0) {
        int wv = (lane < 8) ? swarp[lane] : 0;
        int winc = wv;
#pragma unroll
        for (int o = 1; o < 8; o <<= 1) {
            int x = __shfl_up_sync(0xffffffffu, winc, o);
            if (lane >= o) winc += x;
        }
        swarp[lane] = winc - wv;
    }
    __syncthreads();
    if (t < nb) d_bsum[t] = incl - v + swarp[wid];
}

__global__ __launch_bounds__(SCAN_B) void scan3_kernel(int n, int E) {
    int i = blockIdx.x * SCAN_B + threadIdx.x;
    if (i >= n) return;
    int excl = d_off[i] + d_bsum[blockIdx.x];
    d_off[i] = excl;
    d_cur[i] = excl;
    d_dinv[i] = rsqrtf((float)(d_cnt[i] + 1));
    if (i == n - 1) d_off[n] = E;
}

// ---------------- place edges into CSR (inline decode) ------------------------------
__global__ void place_kernel(const void* __restrict__ ei, int E) {
    int i = blockIdx.x * blockDim.x + threadIdx.x;
    if (i >= E) return;
    int r, c;
    decode_edge(ei, E, i, r, c);
    int pos = atomicAdd(&d_cur[c], 1);
    d_srcs[pos] = r;
}

// ---------------- GEMM: 8 cols x 8 rows per thread; optional fp16 output ------------
// C[i,:] = act( (A[i,:] @ W)*(SCALE?dinv[i]:1) + (BIAS?b:0) )
// Last partial block clamps its base row down; overlapping rows compute
// bit-identical values, so duplicate writes are benign.
template<int K, int NC, bool RELU, bool BIAS, bool SCALE, bool OUT16>
__global__ __launch_bounds__(256, 2) void gemm_kernel(
    const float* __restrict__ A, const float* __restrict__ W,
    const float* __restrict__ bias, void* __restrict__ Cout, int nrows) {
    constexpr int R   = 8;                 // rows per thread
    constexpr int CG  = NC / 8;            // col-groups of 8
    constexpr int RPB = (256 / CG) * R;    // rows per block
    __shared__ float Ws[K * NC];
    for (int t = threadIdx.x; t < K * NC / 4; t += 256)
        ((float4*)Ws)[t] = ((const float4*)W)[t];
    __syncthreads();

    int rg = threadIdx.x / CG;
    int cg = threadIdx.x % CG;
    int r0 = blockIdx.x * RPB + rg * R;
    if (r0 > nrows - R) r0 = nrows - R;    // clamp base (duplicate-safe)

    const float4* Abase = (const float4*)(A + (size_t)r0 * K);

    unsigned long long acc[R][4];
#pragma unroll
    for (int i = 0; i < R; ++i)
#pragma unroll
        for (int j = 0; j < 4; ++j) acc[i][j] = 0ull;

#pragma unroll
    for (int k4 = 0; k4 < K / 4; ++k4) {
        float4 a4[R];
#pragma unroll
        for (int i = 0; i < R; ++i) a4[i] = Abase[i * (K / 4) + k4];
#pragma unroll
        for (int s = 0; s < 4; ++s) {
            int k = k4 * 4 + s;
            const ulonglong2* w2 = (const ulonglong2*)&Ws[k * NC + cg * 8];
            ulonglong2 p0 = w2[0], p1 = w2[1];          // 8 W floats, 2x LDS.128
#pragma unroll
            for (int i = 0; i < R; ++i) {
                float av = (s == 0) ? a4[i].x : (s == 1) ? a4[i].y
                         : (s == 2) ? a4[i].z : a4[i].w;
                unsigned long long ap = pack2(av);
                fma2(acc[i][0], ap, p0.x);
                fma2(acc[i][1], ap, p0.y);
                fma2(acc[i][2], ap, p1.x);
                fma2(acc[i][3], ap, p1.y);
            }
        }
    }

#pragma unroll
    for (int i = 0; i < R; ++i) {
        int r = r0 + i;
        float sc = SCALE ? d_dinv[r] : 1.0f;
#pragma unroll
        for (int q = 0; q < 2; ++q) {
            float2 p0 = unpack2(acc[i][q * 2]);
            float2 p1 = unpack2(acc[i][q * 2 + 1]);
            float4 o = make_float4(p0.x * sc, p0.y * sc, p1.x * sc, p1.y * sc);
            if (BIAS) {
                const float4 bb = *(const float4*)&bias[cg * 8 + q * 4];
                o.x += bb.x; o.y += bb.y; o.z += bb.z; o.w += bb.w;
            }
            if (RELU) {
                o.x = fmaxf(o.x, 0.f); o.y = fmaxf(o.y, 0.f);
                o.z = fmaxf(o.z, 0.f); o.w = fmaxf(o.w, 0.f);
            }
            if (OUT16) {
                __half2 h0 = __float22half2_rn(make_float2(o.x, o.y));
                __half2 h1 = __float22half2_rn(make_float2(o.z, o.w));
                uint2 u;
                u.x = *(const unsigned*)&h0;
                u.y = *(const unsigned*)&h1;
                ((uint2*)((__half*)Cout + (size_t)r * NC + cg * 8))[q] = u;
            } else {
                ((float4*)((float*)Cout + (size_t)r * NC + cg * 8))[q] = o;
            }
        }
    }
}

// ---------------- CSR gather (fp16 src, pipelined index prefetch) -------------------
// SCALE_EDGE=true:  out[c] = relu(dinv[c]*(sum dinv[r]*g[r] + dinv[c]*g[c]) + b)
// SCALE_EDGE=false: out[c] = relu(dinv[c]*(sum g[r] + g[c]) + b)   (g pre-scaled)
// One warp per node; lane owns one half2 (2 cols); 4-edge batches, next batch's
// indices prefetched before consuming this batch's rows.
template<bool SCALE_EDGE>
__global__ __launch_bounds__(256) void gather_csr_kernel(
    const float* __restrict__ b, float* __restrict__ out, __half2* __restrict__ out16,
    int n) {
    int warp = (blockIdx.x * blockDim.x + threadIdx.x) >> 5;
    if (warp >= n) return;
    int lane = threadIdx.x & 31;
    int start = d_off[warp];
    int end   = d_off[warp + 1];
    int col2  = lane * 2;

    float2 acc0 = make_float2(0.f, 0.f), acc1 = make_float2(0.f, 0.f);
    int p = start;
    if (p + 3 < end) {
        int i0 = d_srcs[p], i1 = d_srcs[p + 1], i2 = d_srcs[p + 2], i3 = d_srcs[p + 3];
        while (true) {
            bool more = (p + 7 < end);
            int n0, n1, n2, n3;
            if (more) {           // prefetch next batch's indices
                n0 = d_srcs[p + 4]; n1 = d_srcs[p + 5];
                n2 = d_srcs[p + 6]; n3 = d_srcs[p + 7];
            }
            __half2 v0 = __ldcg((const __half2*)&d_g16[(size_t)i0 * HID + col2]);
            __half2 v1 = __ldcg((const __half2*)&d_g16[(size_t)i1 * HID + col2]);
            __half2 v2 = __ldcg((const __half2*)&d_g16[(size_t)i2 * HID + col2]);
            __half2 v3 = __ldcg((const __half2*)&d_g16[(size_t)i3 * HID + col2]);
            float s0 = 1.f, s1 = 1.f, s2 = 1.f, s3 = 1.f;
            if (SCALE_EDGE) {
                s0 = __ldg(&d_dinv[i0]); s1 = __ldg(&d_dinv[i1]);
                s2 = __ldg(&d_dinv[i2]); s3 = __ldg(&d_dinv[i3]);
            }
            float2 f0 = __half22float2(v0);
            float2 f1 = __half22float2(v1);
            float2 f2 = __half22float2(v2);
            float2 f3 = __half22float2(v3);
            if (SCALE_EDGE) {
                acc0.x = fmaf(s0, f0.x, acc0.x); acc0.y = fmaf(s0, f0.y, acc0.y);
                acc1.x = fmaf(s1, f1.x, acc1.x); acc1.y = fmaf(s1, f1.y, acc1.y);
                acc0.x = fmaf(s2, f2.x, acc0.x); acc0.y = fmaf(s2, f2.y, acc0.y);
                acc1.x = fmaf(s3, f3.x, acc1.x); acc1.y = fmaf(s3, f3.y, acc1.y);
            } else {
                acc0.x += f0.x; acc0.y += f0.y;
                acc1.x += f1.x; acc1.y += f1.y;
                acc0.x += f2.x; acc0.y += f2.y;
                acc1.x += f3.x; acc1.y += f3.y;
            }
            p += 4;
            if (!more) break;
            i0 = n0; i1 = n1; i2 = n2; i3 = n3;
        }
    }
    for (; p < end; ++p) {
        int r0 = d_srcs[p];
        float2 f0 = __half22float2(
            __ldcg((const __half2*)&d_g16[(size_t)r0 * HID + col2]));
        float s0 = SCALE_EDGE ? __ldg(&d_dinv[r0]) : 1.f;
        acc0.x = fmaf(s0, f0.x, acc0.x);
        acc0.y = fmaf(s0, f0.y, acc0.y);
    }
    // self loop + epilogue
    float2 gs = __half22float2(*(const __half2*)&d_g16[(size_t)warp * HID + col2]);
    float di = d_dinv[warp];
    float ss = SCALE_EDGE ? di : 1.f;
    float2 bb = *(const float2*)&b[col2];
    float2 o;
    o.x = fmaxf(di * (acc0.x + acc1.x + ss * gs.x) + bb.x, 0.f);
    o.y = fmaxf(di * (acc0.y + acc1.y + ss * gs.y) + bb.y, 0.f);
    *(float2*)&out[(size_t)warp * HID + col2] = o;
    if (out16) out16[(size_t)warp * (HID / 2) + lane] = __float22half2_rn(o);
}

// ---------------- edge scores from fp16 rows: es[e]=dot(nr[r],nr[c]) (2-edge ILP) ----
__global__ void escore_kernel(const void* __restrict__ ei,
                              const __half2* __restrict__ nr16,
                              float* __restrict__ es, int E, int half) {
    int tid = blockIdx.x * blockDim.x + threadIdx.x;
    int e = tid >> 4;
    if (e >= half) return;
    int l = tid & 15;                       // lane owns halves [4l, 4l+4) = 2 half2
    int r0, c0, r1 = 0, c1 = 0;
    decode_edge(ei, E, e, r0, c0);
    int e1 = e + half;
    bool has2 = (e1 < E);
    if (has2) decode_edge(ei, E, e1, r1, c1);

    uint2 ua0 = __ldcg((const uint2*)&nr16[(size_t)r0 * (HID / 2) + l * 2]);
    uint2 ub0 = __ldcg((const uint2*)&nr16[(size_t)c0 * (HID / 2) + l * 2]);
    uint2 ua1 = make_uint2(0u, 0u), ub1 = make_uint2(0u, 0u);
    if (has2) {
        ua1 = __ldcg((const uint2*)&nr16[(size_t)r1 * (HID / 2) + l * 2]);
        ub1 = __ldcg((const uint2*)&nr16[(size_t)c1 * (HID / 2) + l * 2]);
    }

    float2 a00 = __half22float2(*(const __half2*)&ua0.x);
    float2 a01 = __half22float2(*(const __half2*)&ua0.y);
    float2 b00 = __half22float2(*(const __half2*)&ub0.x);
    float2 b01 = __half22float2(*(const __half2*)&ub0.y);
    float s0 = a00.x * b00.x + a00.y * b00.y + a01.x * b01.x + a01.y * b01.y;

    float2 a10 = __half22float2(*(const __half2*)&ua1.x);
    float2 a11 = __half22float2(*(const __half2*)&ua1.y);
    float2 b10 = __half22float2(*(const __half2*)&ub1.x);
    float2 b11 = __half22float2(*(const __half2*)&ub1.y);
    float s1 = a10.x * b10.x + a10.y * b10.y + a11.x * b11.x + a11.y * b11.y;

#pragma unroll
    for (int m = 8; m >= 1; m >>= 1) {
        s0 += __shfl_xor_sync(0xffffffffu, s0, m);
        s1 += __shfl_xor_sync(0xffffffffu, s1, m);
    }
    if (l == 0) {
        es[e] = s0;
        if (has2) es[e1] = s1;
    }
}

// ---------------- launch ----------------
extern "C" void kernel_launch(void* const* d_in, const int* in_sizes, int n_in,
                              void* d_out, int out_size) {
    const float* x   = (const float*)d_in[0];
    const void*  ei  = d_in[1];
    const float* W1  = (const float*)d_in[2];
    const float* b1  = (const float*)d_in[3];
    const float* W2  = (const float*)d_in[4];
    const float* b2  = (const float*)d_in[5];
    const float* Wd1 = (const float*)d_in[6];
    const float* bd1 = (const float*)d_in[7];
    const float* Wd2 = (const float*)d_in[8];
    const float* bd2 = (const float*)d_in[9];
    float* out = (float*)d_out;

    int Nn = in_sizes[0] / INCH; // 100000
    int Ee = in_sizes[1] / 2;    // 3200000
    int half = (Ee + 1) / 2;

    float* out_rx = out;
    float* out_es = out + (size_t)Nn * INCH;
    float* out_nr = out_es + (size_t)Ee;

    __half* pg16 = nullptr;
    float* ph = nullptr;
    __half2* pnr16 = nullptr;
    cudaGetSymbolAddress((void**)&pg16, d_g16);
    cudaGetSymbolAddress((void**)&ph, d_h);
    cudaGetSymbolAddress((void**)&pnr16, d_nr16);

    const int T = 256;
    int ebl   = (Ee + T - 1) / T;
    int nbl   = (Nn + T - 1) / T;
    int h16bl = (int)(((size_t)half * 16 + T - 1) / T);
    int nwbl  = (int)(((size_t)Nn * 32 + T - 1) / T); // warp per node
    int sbl   = (Nn + SCAN_B - 1) / SCAN_B;           // scan blocks (98)

    cudaStream_t main0 = 0;
    cudaStream_t side = g_ctx.side;

    // #1: detect on the MAIN (captured) stream, then fork side off it.
    detect_kernel<<<1, 32, 0, main0>>>((const unsigned*)ei);
    cudaEventRecord(g_ctx.evA, main0);
    cudaStreamWaitEvent(side, g_ctx.evA, 0);   // capture-legal fork

    // side: full preprocessing chain (all after the fork)
    init_cnt_kernel<<<nbl, T, 0, side>>>(Nn);                 // #2
    hist_kernel<<<ebl, T, 0, side>>>(ei, Ee);                 // #3

    // main: layer-1 GEMM (unscaled, fp16 out) overlaps preprocessing  #4 (ncu slot)
    gemm_kernel<INCH, HID, false, false, false, true>
        <<<(Nn + 255) / 256, T, 0, main0>>>(x, W1, nullptr, pg16, Nn);

    scan1_kernel<<<sbl, SCAN_B, 0, side>>>(Nn);               // #5
    scan2_kernel<<<1, 256, 0, side>>>(sbl);                   // #6
    scan3_kernel<<<sbl, SCAN_B, 0, side>>>(Nn, Ee);           // #7
    place_kernel<<<ebl, T, 0, side>>>(ei, Ee);                // #8
    cudaEventRecord(g_ctx.evB, side);      // CSR + dinv ready

    // gather1 applies dinv to both edge messages and the self loop (SCALE_EDGE)
    cudaStreamWaitEvent(main0, g_ctx.evB, 0);
    gather_csr_kernel<true><<<nwbl, T, 0, main0>>>(b1, ph, nullptr, Nn);

    // ---- layer 2 -> node_representation (fp32 into out segment + fp16 copy)
    gemm_kernel<HID, HID, false, false, true, true>
        <<<(Nn + 255) / 256, T, 0, main0>>>(ph, W2, nullptr, pg16, Nn);
    gather_csr_kernel<false><<<nwbl, T, 0, main0>>>(b2, out_nr, pnr16, Nn);

    // fork: escore (side, fp16 rows) overlaps decoder GEMMs (main)
    cudaEventRecord(g_ctx.evC, main0);
    cudaStreamWaitEvent(side, g_ctx.evC, 0);
    escore_kernel<<<h16bl, T, 0, side>>>(ei, pnr16, out_es, Ee, half);
    cudaEventRecord(g_ctx.evD, side);

    // ---- decoder: rec = relu(nr@Wd1+bd1) ; rx = rec@Wd2 + bd2  (fp32 throughout)
    gemm_kernel<HID, HID, true, true, false, false>
        <<<(Nn + 255) / 256, T, 0, main0>>>(out_nr, Wd1, bd1, ph, Nn);
    gemm_kernel<HID, INCH, false, true, false, false>
        <<<(Nn + 127) / 128, T, 0, main0>>>(ph, Wd2, bd2, out_rx, Nn);

    // join: everything back on the main stream before harness reads d_out
    cudaStreamWaitEvent(main0, g_ctx.evD, 0);
}

// round 17
// speedup vs baseline: 1.0910x; 1.0910x over previous
#include <cuda_runtime.h>
#include <cuda_fp16.h>

#define NNODES 100000
#define NEDGES 3200000
#define INCH 128
#define HID 64
#define SCAN_B 1024

// ---------------- scratch (static device globals; no allocs allowed) ----------------
__device__ __half d_g16[(size_t)NNODES * HID]; // fp16 messages (gather source)
__device__ float  d_h[(size_t)NNODES * HID];   // layer intermediate (fp32)
__device__ __half d_nr16[(size_t)NNODES * HID];// fp16 copy of node_representation
__device__ float  d_dinv[NNODES];
__device__ int    d_cnt[NNODES];               // in-degree (excl self loop)
__device__ int    d_off[NNODES + 1];           // CSR offsets
__device__ int    d_cur[NNODES];               // placement cursors
__device__ int    d_bsum[256];                 // per-block scan partials
__device__ int    d_srcs[NEDGES];              // CSR: source node per incoming edge
__device__ int    g_idx64;

// ---------------- side stream + events for fork/join (created once, host-side) ------
struct SideCtx {
    cudaStream_t side;
    cudaEvent_t evA, evS, evB, evC, evD;
    SideCtx() {
        cudaStreamCreateWithFlags(&side, cudaStreamNonBlocking);
        cudaEventCreateWithFlags(&evA, cudaEventDisableTiming);
        cudaEventCreateWithFlags(&evS, cudaEventDisableTiming);
        cudaEventCreateWithFlags(&evB, cudaEventDisableTiming);
        cudaEventCreateWithFlags(&evC, cudaEventDisableTiming);
        cudaEventCreateWithFlags(&evD, cudaEventDisableTiming);
    }
};
static SideCtx g_ctx;

// ---------------- helpers ----------------
__device__ __forceinline__ unsigned long long pack2(float v) {
    unsigned long long r;
    asm("mov.b64 %0, {%1, %1};" : "=l"(r) : "f"(v));
    return r;
}
__device__ __forceinline__ void fma2(unsigned long long& acc, unsigned long long a,
                                     unsigned long long b) {
    asm("fma.rn.f32x2 %0, %1, %2, %0;" : "+l"(acc) : "l"(a), "l"(b));
}
__device__ __forceinline__ float2 unpack2(unsigned long long v) {
    float2 r;
    asm("mov.b64 {%0, %1}, %2;" : "=f"(r.x), "=f"(r.y) : "l"(v));
    return r;
}
__device__ __forceinline__ void decode_edge(const void* ei, int E, int i,
                                            int& r, int& c) {
    if (g_idx64) {
        const long long* p = (const long long*)ei;
        r = (int)p[i];
        c = (int)p[(size_t)E + i];
    } else {
        const int* p = (const int*)ei;
        r = p[i];
        c = p[(size_t)E + i];
    }
}
__device__ __forceinline__ int decode_col(const void* ei, int E, int i) {
    if (g_idx64) return (int)((const long long*)ei)[(size_t)E + i];
    return ((const int*)ei)[(size_t)E + i];
}

// ---------------- dtype detection: int64 edge_index has zero high words --------------
__global__ void detect_kernel(const unsigned* __restrict__ ei) {
    unsigned v = 0;
    int i = threadIdx.x;
#pragma unroll
    for (int s = 0; s < 4; ++s) v |= ei[(size_t)(i * 4 + s) * 2 + 1];
    unsigned any = __ballot_sync(0xffffffffu, v != 0);
    if (threadIdx.x == 0) g_idx64 = (any == 0) ? 1 : 0;
}

__global__ void init_cnt_kernel(int n) {
    int i = blockIdx.x * blockDim.x + threadIdx.x;
    if (i < n) d_cnt[i] = 0;
}

// ---------------- in-degree histogram (inline decode) -------------------------------
__global__ void hist_kernel(const void* __restrict__ ei, int E) {
    int i = blockIdx.x * blockDim.x + threadIdx.x;
    if (i >= E) return;
    atomicAdd(&d_cnt[decode_col(ei, E, i)], 1);
}

// ---------------- multi-block exclusive scan: 3 phases -------------------------------
__global__ __launch_bounds__(SCAN_B) void scan1_kernel(int n) {
    __shared__ int swarp[32];
    int t = threadIdx.x, lane = t & 31, wid = t >> 5;
    int i = blockIdx.x * SCAN_B + t;
    int v = (i < n) ? d_cnt[i] : 0;
    int incl = v;
#pragma unroll
    for (int o = 1; o < 32; o <<= 1) {
        int x = __shfl_up_sync(0xffffffffu, incl, o);
        if (lane >= o) incl += x;
    }
    if (lane == 31) swarp[wid] = incl;
    __syncthreads();
    if (wid == 0) {
        int wv = swarp[lane];
        int winc = wv;
#pragma unroll
        for (int o = 1; o < 32; o <<= 1) {
            int x = __shfl_up_sync(0xffffffffu, winc, o);
            if (lane >= o) winc += x;
        }
        swarp[lane] = winc - wv;
        if (lane == 31) d_bsum[blockIdx.x] = winc;
    }
    __syncthreads();
    if (i < n) d_off[i] = incl - v + swarp[wid];
}

__global__ void scan2_kernel(int nb) {
    __shared__ int swarp[32];
    int t = threadIdx.x, lane = t & 31, wid = t >> 5; // 256 threads
    int v = (t < nb) ? d_bsum[t] : 0;
    int incl = v;
#pragma unroll
    for (int o = 1; o < 32; o <<= 1) {
        int x = __shfl_up_sync(0xffffffffu, incl, o);
        if (lane >= o) incl += x;
    }
    if (lane == 31) swarp[wid] = incl;
    __syncthreads();
    if (wid == 0) {
        int wv = (lane < 8) ? swarp[lane] : 0;
        int winc = wv;
#pragma unroll
        for (int o = 1; o < 8; o <<= 1) {
            int x = __shfl_up_sync(0xffffffffu, winc, o);
            if (lane >= o) winc += x;
        }
        swarp[lane] = winc - wv;
    }
    __syncthreads();
    if (t < nb) d_bsum[t] = incl - v + swarp[wid];
}

__global__ __launch_bounds__(SCAN_B) void scan3_kernel(int n, int E) {
    int i = blockIdx.x * SCAN_B + threadIdx.x;
    if (i >= n) return;
    int excl = d_off[i] + d_bsum[blockIdx.x];
    d_off[i] = excl;
    d_cur[i] = excl;
    d_dinv[i] = rsqrtf((float)(d_cnt[i] + 1));
    if (i == n - 1) d_off[n] = E;
}

// ---------------- place edges into CSR (inline decode) ------------------------------
__global__ void place_kernel(const void* __restrict__ ei, int E) {
    int i = blockIdx.x * blockDim.x + threadIdx.x;
    if (i >= E) return;
    int r, c;
    decode_edge(ei, E, i, r, c);
    int pos = atomicAdd(&d_cur[c], 1);
    d_srcs[pos] = r;
}

// ---------------- scale fp16 g rows by dinv (post-gemm1, post-scan) -----------------
// Each thread handles 4 halves (8B = uint2) of one row.
__global__ void scale_g_kernel(int n) {
    int idx = blockIdx.x * blockDim.x + threadIdx.x; // over n*16 groups of 4 halves
    if (idx >= n * 16) return;
    float di = d_dinv[idx >> 4];
    uint2* p = (uint2*)&d_g16[(size_t)idx * 4];
    uint2 u = *p;
    float2 f0 = __half22float2(*(const __half2*)&u.x);
    float2 f1 = __half22float2(*(const __half2*)&u.y);
    f0.x *= di; f0.y *= di; f1.x *= di; f1.y *= di;
    __half2 h0 = __float22half2_rn(f0);
    __half2 h1 = __float22half2_rn(f1);
    u.x = *(const unsigned*)&h0;
    u.y = *(const unsigned*)&h1;
    *p = u;
}

// ---------------- GEMM: 8 cols x 8 rows per thread; optional fp16 output ------------
// C[i,:] = act( (A[i,:] @ W)*(SCALE?dinv[i]:1) + (BIAS?b:0) )
// Last partial block clamps its base row down; overlapping rows compute
// bit-identical values, so duplicate writes are benign.
template<int K, int NC, bool RELU, bool BIAS, bool SCALE, bool OUT16>
__global__ __launch_bounds__(256, 2) void gemm_kernel(
    const float* __restrict__ A, const float* __restrict__ W,
    const float* __restrict__ bias, void* __restrict__ Cout, int nrows) {
    constexpr int R   = 8;                 // rows per thread
    constexpr int CG  = NC / 8;            // col-groups of 8
    constexpr int RPB = (256 / CG) * R;    // rows per block
    __shared__ float Ws[K * NC];
    for (int t = threadIdx.x; t < K * NC / 4; t += 256)
        ((float4*)Ws)[t] = ((const float4*)W)[t];
    __syncthreads();

    int rg = threadIdx.x / CG;
    int cg = threadIdx.x % CG;
    int r0 = blockIdx.x * RPB + rg * R;
    if (r0 > nrows - R) r0 = nrows - R;    // clamp base (duplicate-safe)

    const float4* Abase = (const float4*)(A + (size_t)r0 * K);

    unsigned long long acc[R][4];
#pragma unroll
    for (int i = 0; i < R; ++i)
#pragma unroll
        for (int j = 0; j < 4; ++j) acc[i][j] = 0ull;

#pragma unroll
    for (int k4 = 0; k4 < K / 4; ++k4) {
        float4 a4[R];
#pragma unroll
        for (int i = 0; i < R; ++i) a4[i] = Abase[i * (K / 4) + k4];
#pragma unroll
        for (int s = 0; s < 4; ++s) {
            int k = k4 * 4 + s;
            const ulonglong2* w2 = (const ulonglong2*)&Ws[k * NC + cg * 8];
            ulonglong2 p0 = w2[0], p1 = w2[1];          // 8 W floats, 2x LDS.128
#pragma unroll
            for (int i = 0; i < R; ++i) {
                float av = (s == 0) ? a4[i].x : (s == 1) ? a4[i].y
                         : (s == 2) ? a4[i].z : a4[i].w;
                unsigned long long ap = pack2(av);
                fma2(acc[i][0], ap, p0.x);
                fma2(acc[i][1], ap, p0.y);
                fma2(acc[i][2], ap, p1.x);
                fma2(acc[i][3], ap, p1.y);
            }
        }
    }

#pragma unroll
    for (int i = 0; i < R; ++i) {
        int r = r0 + i;
        float sc = SCALE ? d_dinv[r] : 1.0f;
#pragma unroll
        for (int q = 0; q < 2; ++q) {
            float2 p0 = unpack2(acc[i][q * 2]);
            float2 p1 = unpack2(acc[i][q * 2 + 1]);
            float4 o = make_float4(p0.x * sc, p0.y * sc, p1.x * sc, p1.y * sc);
            if (BIAS) {
                const float4 bb = *(const float4*)&bias[cg * 8 + q * 4];
                o.x += bb.x; o.y += bb.y; o.z += bb.z; o.w += bb.w;
            }
            if (RELU) {
                o.x = fmaxf(o.x, 0.f); o.y = fmaxf(o.y, 0.f);
                o.z = fmaxf(o.z, 0.f); o.w = fmaxf(o.w, 0.f);
            }
            if (OUT16) {
                __half2 h0 = __float22half2_rn(make_float2(o.x, o.y));
                __half2 h1 = __float22half2_rn(make_float2(o.z, o.w));
                uint2 u;
                u.x = *(const unsigned*)&h0;
                u.y = *(const unsigned*)&h1;
                ((uint2*)((__half*)Cout + (size_t)r * NC + cg * 8))[q] = u;
            } else {
                ((float4*)((float*)Cout + (size_t)r * NC + cg * 8))[q] = o;
            }
        }
    }
}

// ---------------- CSR gather (fp16 src): 2 nodes/warp, 16 lanes/node ----------------
// out[c] = relu(dinv[c]*(sum_in g[r] + g[c]) + b); g pre-scaled by dinv.
// Each lane owns 4 feature columns (one uint2 = 2 half2); 4-edge unroll per node;
// two independent node chains per warp double the in-flight loads.
__global__ __launch_bounds__(256) void gather_csr_kernel(
    const float* __restrict__ b, float* __restrict__ out, __half2* __restrict__ out16,
    int n) {
    int gtid = blockIdx.x * blockDim.x + threadIdx.x;
    int lane = threadIdx.x & 31;
    int node = (gtid >> 5) * 2 + (lane >> 4);
    if (node >= n) return;
    int l16 = lane & 15;
    int col4 = l16 * 4;
    int start = d_off[node];
    int end   = d_off[node + 1];

    float2 a00 = make_float2(0.f, 0.f), a01 = make_float2(0.f, 0.f);
    float2 a10 = make_float2(0.f, 0.f), a11 = make_float2(0.f, 0.f);
    int p = start;
    for (; p + 3 < end; p += 4) {
        int r0 = d_srcs[p];
        int r1 = d_srcs[p + 1];
        int r2 = d_srcs[p + 2];
        int r3 = d_srcs[p + 3];
        uint2 u0 = __ldcg((const uint2*)&d_g16[(size_t)r0 * HID + col4]);
        uint2 u1 = __ldcg((const uint2*)&d_g16[(size_t)r1 * HID + col4]);
        uint2 u2 = __ldcg((const uint2*)&d_g16[(size_t)r2 * HID + col4]);
        uint2 u3 = __ldcg((const uint2*)&d_g16[(size_t)r3 * HID + col4]);
        float2 f;
        f = __half22float2(*(const __half2*)&u0.x); a00.x += f.x; a00.y += f.y;
        f = __half22float2(*(const __half2*)&u0.y); a01.x += f.x; a01.y += f.y;
        f = __half22float2(*(const __half2*)&u1.x); a10.x += f.x; a10.y += f.y;
        f = __half22float2(*(const __half2*)&u1.y); a11.x += f.x; a11.y += f.y;
        f = __half22float2(*(const __half2*)&u2.x); a00.x += f.x; a00.y += f.y;
        f = __half22float2(*(const __half2*)&u2.y); a01.x += f.x; a01.y += f.y;
        f = __half22float2(*(const __half2*)&u3.x); a10.x += f.x; a10.y += f.y;
        f = __half22float2(*(const __half2*)&u3.y); a11.x += f.x; a11.y += f.y;
    }
    for (; p < end; ++p) {
        int r0 = d_srcs[p];
        uint2 u0 = __ldcg((const uint2*)&d_g16[(size_t)r0 * HID + col4]);
        float2 f;
        f = __half22float2(*(const __half2*)&u0.x); a00.x += f.x; a00.y += f.y;
        f = __half22float2(*(const __half2*)&u0.y); a01.x += f.x; a01.y += f.y;
    }
    // self loop + epilogue
    uint2 us = *(const uint2*)&d_g16[(size_t)node * HID + col4];
    float2 g0 = __half22float2(*(const __half2*)&us.x);
    float2 g1 = __half22float2(*(const __half2*)&us.y);
    float di = d_dinv[node];
    float4 bb = *(const float4*)&b[col4];
    float4 o;
    o.x = fmaxf(di * (a00.x + a10.x + g0.x) + bb.x, 0.f);
    o.y = fmaxf(di * (a00.y + a10.y + g0.y) + bb.y, 0.f);
    o.z = fmaxf(di * (a01.x + a11.x + g1.x) + bb.z, 0.f);
    o.w = fmaxf(di * (a01.y + a11.y + g1.y) + bb.w, 0.f);
    *(float4*)&out[(size_t)node * HID + col4] = o;
    if (out16) {
        __half2 h0 = __float22half2_rn(make_float2(o.x, o.y));
        __half2 h1 = __float22half2_rn(make_float2(o.z, o.w));
        uint2 u;
        u.x = *(const unsigned*)&h0;
        u.y = *(const unsigned*)&h1;
        *(uint2*)&d_nr16[(size_t)node * HID + col4] = u;
    }
}

// ---------------- edge scores from fp16 rows: es[e]=dot(nr[r],nr[c]) (2-edge ILP) ----
__global__ void escore_kernel(const void* __restrict__ ei,
                              const __half2* __restrict__ nr16,
                              float* __restrict__ es, int E, int half) {
    int tid = blockIdx.x * blockDim.x + threadIdx.x;
    int e = tid >> 4;
    if (e >= half) return;
    int l = tid & 15;                       // lane owns halves [4l, 4l+4) = 2 half2
    int r0, c0, r1 = 0, c1 = 0;
    decode_edge(ei, E, e, r0, c0);
    int e1 = e + half;
    bool has2 = (e1 < E);
    if (has2) decode_edge(ei, E, e1, r1, c1);

    uint2 ua0 = __ldcg((const uint2*)&nr16[(size_t)r0 * (HID / 2) + l * 2]);
    uint2 ub0 = __ldcg((const uint2*)&nr16[(size_t)c0 * (HID / 2) + l * 2]);
    uint2 ua1 = make_uint2(0u, 0u), ub1 = make_uint2(0u, 0u);
    if (has2) {
        ua1 = __ldcg((const uint2*)&nr16[(size_t)r1 * (HID / 2) + l * 2]);
        ub1 = __ldcg((const uint2*)&nr16[(size_t)c1 * (HID / 2) + l * 2]);
    }

    float2 a00 = __half22float2(*(const __half2*)&ua0.x);
    float2 a01 = __half22float2(*(const __half2*)&ua0.y);
    float2 b00 = __half22float2(*(const __half2*)&ub0.x);
    float2 b01 = __half22float2(*(const __half2*)&ub0.y);
    float s0 = a00.x * b00.x + a00.y * b00.y + a01.x * b01.x + a01.y * b01.y;

    float2 a10 = __half22float2(*(const __half2*)&ua1.x);
    float2 a11 = __half22float2(*(const __half2*)&ua1.y);
    float2 b10 = __half22float2(*(const __half2*)&ub1.x);
    float2 b11 = __half22float2(*(const __half2*)&ub1.y);
    float s1 = a10.x * b10.x + a10.y * b10.y + a11.x * b11.x + a11.y * b11.y;

#pragma unroll
    for (int m = 8; m >= 1; m >>= 1) {
        s0 += __shfl_xor_sync(0xffffffffu, s0, m);
        s1 += __shfl_xor_sync(0xffffffffu, s1, m);
    }
    if (l == 0) {
        es[e] = s0;
        if (has2) es[e1] = s1;
    }
}

// ---------------- launch ----------------
extern "C" void kernel_launch(void* const* d_in, const int* in_sizes, int n_in,
                              void* d_out, int out_size) {
    const float* x   = (const float*)d_in[0];
    const void*  ei  = d_in[1];
    const float* W1  = (const float*)d_in[2];
    const float* b1  = (const float*)d_in[3];
    const float* W2  = (const float*)d_in[4];
    const float* b2  = (const float*)d_in[5];
    const float* Wd1 = (const float*)d_in[6];
    const float* bd1 = (const float*)d_in[7];
    const float* Wd2 = (const float*)d_in[8];
    const float* bd2 = (const float*)d_in[9];
    float* out = (float*)d_out;

    int Nn = in_sizes[0] / INCH; // 100000
    int Ee = in_sizes[1] / 2;    // 3200000
    int half = (Ee + 1) / 2;

    float* out_rx = out;
    float* out_es = out + (size_t)Nn * INCH;
    float* out_nr = out_es + (size_t)Ee;

    __half* pg16 = nullptr;
    float* ph = nullptr;
    __half2* pnr16 = nullptr;
    cudaGetSymbolAddress((void**)&pg16, d_g16);
    cudaGetSymbolAddress((void**)&ph, d_h);
    cudaGetSymbolAddress((void**)&pnr16, d_nr16);

    const int T = 256;
    int ebl   = (Ee + T - 1) / T;
    int nbl   = (Nn + T - 1) / T;
    int h16bl = (int)(((size_t)half * 16 + T - 1) / T);
    int n16bl = (int)(((size_t)Nn * 16 + T - 1) / T);
    int nwbl  = (int)(((size_t)((Nn + 1) / 2) * 32 + T - 1) / T); // warp per 2 nodes
    int sbl   = (Nn + SCAN_B - 1) / SCAN_B;           // scan blocks (98)

    cudaStream_t main0 = 0;
    cudaStream_t side = g_ctx.side;

    // #1: detect on the MAIN (captured) stream, then fork side off it.
    detect_kernel<<<1, 32, 0, main0>>>((const unsigned*)ei);
    cudaEventRecord(g_ctx.evA, main0);
    cudaStreamWaitEvent(side, g_ctx.evA, 0);   // capture-legal fork

    // side: full preprocessing chain (all after the fork)
    init_cnt_kernel<<<nbl, T, 0, side>>>(Nn);                 // #2
    hist_kernel<<<ebl, T, 0, side>>>(ei, Ee);                 // #3

    // main: layer-1 GEMM (unscaled, fp16 out) overlaps preprocessing  #4 (ncu slot)
    gemm_kernel<INCH, HID, false, false, false, true>
        <<<(Nn + 255) / 256, T, 0, main0>>>(x, W1, nullptr, pg16, Nn);

    scan1_kernel<<<sbl, SCAN_B, 0, side>>>(Nn);               // #5
    scan2_kernel<<<1, 256, 0, side>>>(sbl);                   // #6
    scan3_kernel<<<sbl, SCAN_B, 0, side>>>(Nn, Ee);           // #7
    cudaEventRecord(g_ctx.evS, side);      // dinv + offsets ready
    place_kernel<<<ebl, T, 0, side>>>(ei, Ee);                // #8
    cudaEventRecord(g_ctx.evB, side);      // CSR ready

    cudaStreamWaitEvent(main0, g_ctx.evS, 0);
    scale_g_kernel<<<n16bl, T, 0, main0>>>(Nn);      // g16 *= dinv (fp16 in place)
    cudaStreamWaitEvent(main0, g_ctx.evB, 0);
    gather_csr_kernel<<<nwbl, T, 0, main0>>>(b1, ph, nullptr, Nn);

    // ---- layer 2 -> node_representation (fp32 into out segment + fp16 copy)
    gemm_kernel<HID, HID, false, false, true, true>
        <<<(Nn + 255) / 256, T, 0, main0>>>(ph, W2, nullptr, pg16, Nn);
    gather_csr_kernel<<<nwbl, T, 0, main0>>>(b2, out_nr, pnr16, Nn);

    // fork: escore (side, fp16 rows) overlaps decoder GEMMs (main)
    cudaEventRecord(g_ctx.evC, main0);
    cudaStreamWaitEvent(side, g_ctx.evC, 0);
    escore_kernel<<<h16bl, T, 0, side>>>(ei, pnr16, out_es, Ee, half);
    cudaEventRecord(g_ctx.evD, side);

    // ---- decoder: rec = relu(nr@Wd1+bd1) ; rx = rec@Wd2 + bd2  (fp32 throughout)
    gemm_kernel<HID, HID, true, true, false, false>
        <<<(Nn + 255) / 256, T, 0, main0>>>(out_nr, Wd1, bd1, ph, Nn);
    gemm_kernel<HID, INCH, false, true, false, false>
        <<<(Nn + 127) / 128, T, 0, main0>>>(ph, Wd2, bd2, out_rx, Nn);

    // join: everything back on the main stream before harness reads d_out
    cudaStreamWaitEvent(main0, g_ctx.evD, 0);
}